// round 13
// baseline (speedup 1.0000x reference)
#include <cuda_runtime.h>
#include <cuda_bf16.h>
#include <cstdint>

typedef unsigned long long u64;

#define Tn 32768
#define Kn 8192
#define Dn 128
#define DECAYc 0.1f
#define OMD 0.9f
#define EPSc 1e-5f

// output element offsets (float32 concat in reference return order)
#define OFF_Q    0ll
#define OFF_IDX  4194304ll            // T*D
#define OFF_DIST 4227072ll            // + T
#define OFF_NE   272662528ll          // + T*K
#define OFF_NCS  273711104ll          // + K*D
#define OFF_NEA  273719296ll          // + K

// smem: x2s f32[128] @0 | A @2048 (128x136 bf16) | B0 @36864 (64x136) | B1 @54272
#define A_OFF 2048
#define B0_OFF 36864
#define B1_OFF 54272
#define ROWB  272                      // 136 bf16 padded row stride (bytes)
#define GEMM_SMEM 71680
#define NITER 16                       // 64-col tiles per CTA (CTA covers 1024 cols)

__device__ int   g_tilemin[(size_t)Tn * 64];     // float bits per 128-col tile, min via atomic s32
__device__ float g_x2[Tn];
__device__ float g_e2[Kn];
__device__ float g_cs[Kn];
__device__ float g_es[(size_t)Kn * Dn];
__device__ float g_sum_cs;
__device__ __nv_bfloat16 g_xb[(size_t)Tn * Dn];
__device__ __nv_bfloat16 g_eb[(size_t)Kn * Dn];

__device__ __forceinline__ uint32_t sm_u32(const void* p) {
    uint32_t a;
    asm("{ .reg .u64 t; cvta.to.shared.u64 t, %1; cvt.u32.u64 %0, t; }" : "=r"(a) : "l"(p));
    return a;
}
__device__ __forceinline__ void cpa16(uint32_t s, const void* g) {
    asm volatile("cp.async.cg.shared.global [%0], [%1], 16;\n" :: "r"(s), "l"(g));
}
__device__ __forceinline__ void ldsm4(uint32_t* r, uint32_t a) {
    asm volatile("ldmatrix.sync.aligned.m8n8.x4.shared.b16 {%0,%1,%2,%3}, [%4];"
                 : "=r"(r[0]), "=r"(r[1]), "=r"(r[2]), "=r"(r[3]) : "r"(a));
}
__device__ __forceinline__ void mma_bf16(float* c, const uint32_t* a, const uint32_t* b) {
    asm volatile(
        "mma.sync.aligned.m16n8k16.row.col.f32.bf16.bf16.f32 "
        "{%0,%1,%2,%3},{%4,%5,%6,%7},{%8,%9},{%0,%1,%2,%3};\n"
        : "+f"(c[0]), "+f"(c[1]), "+f"(c[2]), "+f"(c[3])
        : "r"(a[0]), "r"(a[1]), "r"(a[2]), "r"(a[3]), "r"(b[0]), "r"(b[1]));
}
__device__ __forceinline__ void stg_cs_v4(float* p, float a, float b, float c, float d) {
    asm volatile("st.global.cs.v4.f32 [%0], {%1,%2,%3,%4};"
                 :: "l"(p), "f"(a), "f"(b), "f"(c), "f"(d) : "memory");
}

// B-row permutation within a 16-row group: MMA n-index -> codebook col so that
// thread q = lane&3 holds 4 consecutive cols. n = (nt<<3)|(q<<1)|i -> c = (q<<2)|(nt<<1)|i
__device__ __forceinline__ int permB16(int n) {
    return (((n >> 1) & 3) << 2) | (((n >> 3) & 1) << 1) | (n & 1);
}

// ---------------- init scratch ----------------
__global__ void init_misc_kernel() {
    size_t i = (size_t)blockIdx.x * 256 + threadIdx.x;
    if (i < (size_t)Kn * Dn) g_es[i] = 0.0f;
    if (i < Kn) g_cs[i] = 0.0f;
    if (i == 0) g_sum_cs = 0.0f;
}
__global__ void init_tilemin_kernel() {
    size_t i = (size_t)blockIdx.x * 256 + threadIdx.x;
    if (i < (size_t)Tn * 64) g_tilemin[i] = 0x7F7FFFFF;   // FLT_MAX bits
}

// ---------------- fp32->bf16 convert + row norms + cs_in sum ----------------
__global__ void convert_kernel(const float* __restrict__ x, const float* __restrict__ e,
                               const float* __restrict__ csz) {
    int w = (blockIdx.x * blockDim.x + threadIdx.x) >> 5;
    int lane = threadIdx.x & 31;
    if (w >= Tn + Kn) return;
    const float* src;
    __nv_bfloat16* dst;
    if (w < Tn) { src = x + (size_t)w * Dn; dst = g_xb + (size_t)w * Dn; }
    else        { src = e + (size_t)(w - Tn) * Dn; dst = g_eb + (size_t)(w - Tn) * Dn; }
    float4 v = ((const float4*)src)[lane];
    float s = v.x * v.x + v.y * v.y + v.z * v.z + v.w * v.w;
    #pragma unroll
    for (int sh = 16; sh; sh >>= 1) s += __shfl_xor_sync(0xffffffffu, s, sh);
    if (lane == 0) {
        if (w < Tn) g_x2[w] = s;
        else {
            g_e2[w - Tn] = s;
            atomicAdd(&g_sum_cs, csz[w - Tn]);
        }
    }
    __nv_bfloat162 p0 = __floats2bfloat162_rn(v.x, v.y);
    __nv_bfloat162 p1 = __floats2bfloat162_rn(v.z, v.w);
    ((__nv_bfloat162*)dst)[lane * 2]     = p0;
    ((__nv_bfloat162*)dst)[lane * 2 + 1] = p1;
}

// ---------------- bf16 HMMA GEMM, A-resident, 16 x 64-col iters, 3 CTAs/SM ----------------
__global__ void __launch_bounds__(256, 3)
gemm_kernel(float* __restrict__ out) {
    extern __shared__ char smraw[];
    float* x2s = (float*)smraw;
    const uint32_t abase = sm_u32(smraw);
    const uint32_t Abase = abase + A_OFF;
    const uint32_t Bbase[2] = { abase + B0_OFF, abase + B1_OFF };

    const int tid = threadIdx.x;
    const int lane = tid & 31, warp = tid >> 5;
    const int wm = warp >> 2, wn = warp & 3;          // 2 x 4 warp grid, warp tile 64x16
    const int ptid = (wm << 5) | lane;                // 0..63 within pair
    const int q = lane & 3;
    const int bx = blockIdx.x, by = blockIdx.y;
    const int rowBase = by * 128;
    const int col0 = bx * (64 * NITER);               // CTA covers 1024 cols

    const __nv_bfloat16* xg = g_xb + (size_t)rowBase * Dn;

    // group 0: A tile (128x128 bf16), all 256 threads
    #pragma unroll
    for (int i = 0; i < 8; i++) {
        int idx = tid + i * 256;
        int r = idx >> 4, f = idx & 15;
        cpa16(Abase + r * ROWB + f * 16, xg + (size_t)r * Dn + f * 8);
    }
    asm volatile("cp.async.commit_group;\n");

    // groups 1,2: this pair's 16-row slice of B tiles 0,1 (rows permuted within group)
    #pragma unroll
    for (int pb = 0; pb < 2; pb++) {
        const __nv_bfloat16* eg = g_eb + (size_t)(col0 + pb * 64) * Dn;
        #pragma unroll
        for (int i = 0; i < 4; i++) {
            int idx = ptid + i * 64;                  // 0..255
            int rl = idx >> 4, f = idx & 15;          // local row 0..15
            int rs = (wn << 4) + rl;                  // smem row
            int rc = (wn << 4) + permB16(rl);         // codebook row
            cpa16(Bbase[pb] + rs * ROWB + f * 16, eg + (size_t)rc * Dn + f * 8);
        }
        asm volatile("cp.async.commit_group;\n");
    }

    if (tid < 128) x2s[tid] = g_x2[rowBase + tid];

    asm volatile("cp.async.wait_group 2;\n");         // A resident
    __syncthreads();

    const uint32_t aoff = (uint32_t)(lane & 15) * ROWB + ((uint32_t)(lane >> 4) << 4);
    const uint32_t boff = ((((uint32_t)lane >> 4) << 3) + (lane & 7)) * ROWB + (((lane >> 3) & 1) << 4);
    const uint32_t Aw = Abase + (wm * 64) * ROWB + aoff;

    float* dist = out + OFF_DIST;

    #pragma unroll 1
    for (int it = 0; it < NITER; it++) {
        if (it < NITER - 1) asm volatile("cp.async.wait_group 1;\n");
        else                asm volatile("cp.async.wait_group 0;\n");
        asm volatile("bar.sync %0, 64;" :: "r"(1 + wn) : "memory");   // pair's B(it) slice visible

        const int colBase = col0 + it * 64;
        const int tileIdx = (colBase >> 7);           // 128-col tilemin slot (2 iters share one)

        float e2v[4];
        #pragma unroll
        for (int j = 0; j < 4; j++)
            e2v[j] = __ldg(&g_e2[colBase + wn * 16 + 4 * q + j]);

        const uint32_t Bw = Bbase[it & 1] + (wn * 16) * ROWB + boff;
        float acc[4][2][4] = {};
        #pragma unroll
        for (int ks = 0; ks < 8; ks++) {
            const uint32_t kb = ks * 32;
            uint32_t a[4][4], b[4];
            #pragma unroll
            for (int mt = 0; mt < 4; mt++) ldsm4(a[mt], Aw + mt * (16 * ROWB) + kb);
            ldsm4(b, Bw + kb);
            #pragma unroll
            for (int mt = 0; mt < 4; mt++) {
                mma_bf16(acc[mt][0], a[mt], &b[0]);
                mma_bf16(acc[mt][1], a[mt], &b[2]);
            }
        }

        // epilogue: dist = x2 + e2 - 2*dot; thread holds 4 consecutive cols per (mt,half)
        #pragma unroll
        for (int mt = 0; mt < 4; mt++) {
            #pragma unroll
            for (int half = 0; half < 2; half++) {
                int r = wm * 64 + mt * 16 + half * 8 + (lane >> 2);
                size_t grow = (size_t)rowBase + r;
                float x2v = x2s[r];
                float* drow = dist + grow * Kn + colBase + wn * 16 + 4 * q;
                float d0 = fmaf(-2.0f, acc[mt][0][half * 2 + 0], x2v + e2v[0]);
                float d1 = fmaf(-2.0f, acc[mt][0][half * 2 + 1], x2v + e2v[1]);
                float d2 = fmaf(-2.0f, acc[mt][1][half * 2 + 0], x2v + e2v[2]);
                float d3 = fmaf(-2.0f, acc[mt][1][half * 2 + 1], x2v + e2v[3]);
                stg_cs_v4(drow, d0, d1, d2, d3);
                float minv = fminf(fminf(d0, d1), fminf(d2, d3));
                minv = fminf(minv, __shfl_xor_sync(0xffffffffu, minv, 1));
                minv = fminf(minv, __shfl_xor_sync(0xffffffffu, minv, 2));
                if (q == 0)
                    atomicMin(&g_tilemin[grow * 64 + tileIdx], __float_as_int(minv));
            }
        }

        asm volatile("bar.sync %0, 64;" :: "r"(1 + wn) : "memory");   // pair done with buf(it&1)
        if (it + 2 < NITER) {
            const __nv_bfloat16* eg = g_eb + (size_t)(col0 + (it + 2) * 64) * Dn;
            #pragma unroll
            for (int i = 0; i < 4; i++) {
                int idx = ptid + i * 64;
                int rl = idx >> 4, f = idx & 15;
                int rs = (wn << 4) + rl;
                int rc = (wn << 4) + permB16(rl);
                cpa16(Bbase[it & 1] + rs * ROWB + f * 16, eg + (size_t)rc * Dn + f * 8);
            }
        }
        asm volatile("cp.async.commit_group;\n");
    }
}

// ---------------- argmin refine (fast-path + exact fallback) + fused assign ----------------
__global__ void refine_kernel(const float* __restrict__ x, const float* __restrict__ e,
                              float* __restrict__ out) {
    int t = (blockIdx.x * blockDim.x + threadIdx.x) >> 5;
    int lane = threadIdx.x & 31;
    if (t >= Tn) return;
    const float* dist = out + OFF_DIST;

    float4 xa = ((const float4*)(x + (size_t)t * Dn))[lane];
    float m0 = __int_as_float(g_tilemin[(size_t)t * 64 + lane]);
    float m1 = __int_as_float(g_tilemin[(size_t)t * 64 + 32 + lane]);

    float ml = fminf(m0, m1);
    float gm = ml;
    #pragma unroll
    for (int s = 16; s; s >>= 1) gm = fminf(gm, __shfl_xor_sync(0xffffffffu, gm, s));

    unsigned msk = __ballot_sync(0xffffffffu, ml == gm);
    int srcLane = __ffs(msk) - 1;
    int myTile = (m0 <= m1) ? lane : lane + 32;
    int bestTile = __shfl_sync(0xffffffffu, myTile, srcLane);
    float contrib = (lane == srcLane) ? ((m0 <= m1) ? m1 : m0) : ml;
    float secTiles = contrib;
    #pragma unroll
    for (int s = 16; s; s >>= 1) secTiles = fminf(secTiles, __shfl_xor_sync(0xffffffffu, secTiles, s));

    float4 dv = ((const float4*)(dist + (size_t)t * Kn + bestTile * 128))[lane];
    int cb = bestTile * 128 + lane * 4;
    u64 k0 = ((u64)__float_as_uint(dv.x) << 32) | (unsigned)(cb + 0);
    u64 k1 = ((u64)__float_as_uint(dv.y) << 32) | (unsigned)(cb + 1);
    u64 k2 = ((u64)__float_as_uint(dv.z) << 32) | (unsigned)(cb + 2);
    u64 k3 = ((u64)__float_as_uint(dv.w) << 32) | (unsigned)(cb + 3);
    u64 a01 = min(k0, k1), b01 = max(k0, k1);
    u64 a23 = min(k2, k3), b23 = max(k2, k3);
    u64 kb = min(a01, a23);
    float run2 = fminf(__uint_as_float((uint32_t)(max(a01, a23) >> 32)),
                       fminf(__uint_as_float((uint32_t)(b01 >> 32)),
                             __uint_as_float((uint32_t)(b23 >> 32))));
    #pragma unroll
    for (int s = 16; s; s >>= 1) {
        u64 ko = __shfl_xor_sync(0xffffffffu, kb, s);
        float r2o = __shfl_xor_sync(0xffffffffu, run2, s);
        float loserv = __uint_as_float((uint32_t)(max(kb, ko) >> 32));
        run2 = fminf(fminf(run2, r2o), loserv);
        kb = min(kb, ko);
    }
    float bestv = __uint_as_float((uint32_t)(kb >> 32));
    int idx;
    if (fminf(secTiles, run2) - bestv > 0.5f) {
        idx = (int)(kb & 0xffffffffull);
    } else {
        float th = gm + 1.0f;
        float x2v = g_x2[t];
        u64 best = ~0ull;
        #pragma unroll
        for (int j2 = 0; j2 < 2; j2++) {
            float tv = j2 ? m1 : m0;
            unsigned m = __ballot_sync(0xffffffffu, tv < th);
            while (m) {
                int tl = __ffs(m) - 1; m &= m - 1;
                int tile = tl + 32 * j2;
                float4 dd = ((const float4*)(dist + (size_t)t * Kn + tile * 128))[lane];
                float dvals[4] = {dd.x, dd.y, dd.z, dd.w};
                #pragma unroll
                for (int qq = 0; qq < 4; qq++) {
                    unsigned lm = __ballot_sync(0xffffffffu, dvals[qq] < th);
                    while (lm) {
                        int src = __ffs(lm) - 1; lm &= lm - 1;
                        int col = tile * 128 + src * 4 + qq;
                        float4 ev = ((const float4*)(e + (size_t)col * Dn))[lane];
                        float p = xa.x * ev.x + xa.y * ev.y + xa.z * ev.z + xa.w * ev.w;
                        #pragma unroll
                        for (int s = 16; s; s >>= 1) p += __shfl_xor_sync(0xffffffffu, p, s);
                        float dex = x2v + g_e2[col] - 2.0f * p;
                        u64 kk = ((u64)__float_as_uint(dex) << 32) | (u64)(unsigned)col;
                        best = min(best, kk);
                    }
                }
            }
        }
        idx = (int)(best & 0xffffffffull);
    }

    float4 ev = ((const float4*)(e + (size_t)idx * Dn))[lane];
    ((float4*)(out + OFF_Q + (size_t)t * Dn))[lane] = ev;
    float* gp = g_es + (size_t)idx * Dn + lane * 4;
    atomicAdd(gp + 0, xa.x);
    atomicAdd(gp + 1, xa.y);
    atomicAdd(gp + 2, xa.z);
    atomicAdd(gp + 3, xa.w);
    if (lane == 0) {
        out[OFF_IDX + t] = (float)idx;
        atomicAdd(&g_cs[idx], 1.0f);
    }
}

// ---------------- fused EMA: cluster size, embed_avg, laplace-normalized embed ----------------
__global__ void ema_kernel(const float* __restrict__ cs_in, const float* __restrict__ ea,
                           float* __restrict__ out) {
    size_t i = (size_t)blockIdx.x * 256 + threadIdx.x;
    if (i >= (size_t)Kn * Dn) return;
    int k = (int)(i >> 7);
    float ncs = DECAYc * cs_in[k] + OMD * g_cs[k];
    if ((i & 127) == 0) out[OFF_NCS + k] = ncs;
    float nea = DECAYc * ea[i] + OMD * g_es[i];
    out[OFF_NEA + i] = nea;
    float total = DECAYc * g_sum_cs + OMD * (float)Tn;
    float norm = (ncs + EPSc) / (total + (float)Kn * EPSc);
    out[OFF_NE + i] = nea / norm;
}

extern "C" void kernel_launch(void* const* d_in, const int* in_sizes, int n_in,
                              void* d_out, int out_size) {
    const float* x     = (const float*)d_in[0];
    const float* embed = (const float*)d_in[1];
    const float* csz   = (const float*)d_in[2];
    const float* eavg  = (const float*)d_in[3];
    float* out = (float*)d_out;

    cudaFuncSetAttribute(gemm_kernel, cudaFuncAttributeMaxDynamicSharedMemorySize, GEMM_SMEM);

    // order keeps gemm_kernel at launch index 3 (ncu capture slot)
    init_misc_kernel<<<(Kn * Dn) / 256, 256>>>();
    convert_kernel<<<(Tn + Kn) / 8, 256>>>(x, embed, csz);
    init_tilemin_kernel<<<(Tn * 64) / 256, 256>>>();
    gemm_kernel<<<dim3(Kn / (64 * NITER), Tn / 128), 256, GEMM_SMEM>>>(out);
    refine_kernel<<<Tn / 8, 256>>>(x, embed, out);
    ema_kernel<<<(Kn * Dn) / 256, 256>>>(csz, eavg, out);
}

// round 14
// speedup vs baseline: 1.2032x; 1.2032x over previous
#include <cuda_runtime.h>
#include <cuda_bf16.h>
#include <cstdint>

typedef unsigned long long u64;

#define Tn 32768
#define Kn 8192
#define Dn 128
#define DECAYc 0.1f
#define OMD 0.9f
#define EPSc 1e-5f

// output element offsets (float32 concat in reference return order)
#define OFF_Q    0ll
#define OFF_IDX  4194304ll            // T*D
#define OFF_DIST 4227072ll            // + T
#define OFF_NE   272662528ll          // + T*K
#define OFF_NCS  273711104ll          // + K*D
#define OFF_NEA  273719296ll          // + K

// smem: x2s f32[128] @0 | e2s f32[1024] @1024 | A @5120 (128x136 bf16) | B0 @39936 | B1 @74752
#define E2_OFF 1024
#define A_OFF  5120
#define B0_OFF 39936
#define B1_OFF 74752
#define ROWB   272                     // 136 bf16 padded row stride (bytes)
#define GEMM_SMEM 109568
#define SPLIT 8                        // 128-col tiles per CTA (CTA covers 1024 cols)

__device__ int   g_tilemin[(size_t)Tn * 64];     // float bits per 128-col tile, min via atomic s32
__device__ float g_x2[Tn];
__device__ float g_e2[Kn];
__device__ float g_cs[Kn];
__device__ float g_es[(size_t)Kn * Dn];
__device__ float g_sum_cs;
__device__ __nv_bfloat16 g_xb[(size_t)Tn * Dn];
__device__ __nv_bfloat16 g_eb[(size_t)Kn * Dn];

__device__ __forceinline__ uint32_t sm_u32(const void* p) {
    uint32_t a;
    asm("{ .reg .u64 t; cvta.to.shared.u64 t, %1; cvt.u32.u64 %0, t; }" : "=r"(a) : "l"(p));
    return a;
}
__device__ __forceinline__ void cpa16(uint32_t s, const void* g) {
    asm volatile("cp.async.cg.shared.global [%0], [%1], 16;\n" :: "r"(s), "l"(g));
}
__device__ __forceinline__ void ldsm4(uint32_t* r, uint32_t a) {
    asm volatile("ldmatrix.sync.aligned.m8n8.x4.shared.b16 {%0,%1,%2,%3}, [%4];"
                 : "=r"(r[0]), "=r"(r[1]), "=r"(r[2]), "=r"(r[3]) : "r"(a));
}
__device__ __forceinline__ void mma_bf16(float* c, const uint32_t* a, const uint32_t* b) {
    asm volatile(
        "mma.sync.aligned.m16n8k16.row.col.f32.bf16.bf16.f32 "
        "{%0,%1,%2,%3},{%4,%5,%6,%7},{%8,%9},{%0,%1,%2,%3};\n"
        : "+f"(c[0]), "+f"(c[1]), "+f"(c[2]), "+f"(c[3])
        : "r"(a[0]), "r"(a[1]), "r"(a[2]), "r"(a[3]), "r"(b[0]), "r"(b[1]));
}
__device__ __forceinline__ void stg_cs_v4(float* p, float a, float b, float c, float d) {
    asm volatile("st.global.cs.v4.f32 [%0], {%1,%2,%3,%4};"
                 :: "l"(p), "f"(a), "f"(b), "f"(c), "f"(d) : "memory");
}

// B-row permutation: MMA n-index (5 bits) -> codebook col (swap bit pairs)
__device__ __forceinline__ int permB(int n) {
    return (((n >> 1) & 3) << 3) | (((n >> 3) & 3) << 1) | (n & 1);
}

// ---------------- fp32->bf16 convert + row norms + cs_in sum + scratch init (fused) ----------------
__global__ void convert_kernel(const float* __restrict__ x, const float* __restrict__ e,
                               const float* __restrict__ csz) {
    int gtid = blockIdx.x * blockDim.x + threadIdx.x;      // 1,310,720 threads
    // fused init: g_es (1M), g_cs (8K), g_tilemin (2M), g_sum_cs
    if (gtid < Kn * Dn) g_es[gtid] = 0.0f;
    if (gtid < Kn) g_cs[gtid] = 0.0f;
    if (gtid == 0) g_sum_cs = 0.0f;
    g_tilemin[gtid] = 0x7F7FFFFF;
    if (gtid + 1310720 < Tn * 64) g_tilemin[gtid + 1310720] = 0x7F7FFFFF;

    int w = gtid >> 5;
    int lane = threadIdx.x & 31;
    if (w >= Tn + Kn) return;
    const float* src;
    __nv_bfloat16* dst;
    if (w < Tn) { src = x + (size_t)w * Dn; dst = g_xb + (size_t)w * Dn; }
    else        { src = e + (size_t)(w - Tn) * Dn; dst = g_eb + (size_t)(w - Tn) * Dn; }
    float4 v = ((const float4*)src)[lane];
    float s = v.x * v.x + v.y * v.y + v.z * v.z + v.w * v.w;
    #pragma unroll
    for (int sh = 16; sh; sh >>= 1) s += __shfl_xor_sync(0xffffffffu, s, sh);
    if (lane == 0) {
        if (w < Tn) g_x2[w] = s;
        else {
            g_e2[w - Tn] = s;
            atomicAdd(&g_sum_cs, csz[w - Tn]);
        }
    }
    __nv_bfloat162 p0 = __floats2bfloat162_rn(v.x, v.y);
    __nv_bfloat162 p1 = __floats2bfloat162_rn(v.z, v.w);
    ((__nv_bfloat162*)dst)[lane * 2]     = p0;
    ((__nv_bfloat162*)dst)[lane * 2 + 1] = p1;
}

// ---------------- bf16 HMMA GEMM, A-resident, pair-scoped single-barrier pipeline ----------------
__global__ void __launch_bounds__(256, 2)
gemm_kernel(float* __restrict__ out) {
    extern __shared__ char smraw[];
    float* x2s = (float*)smraw;
    float* e2s = (float*)(smraw + E2_OFF);
    const uint32_t abase = sm_u32(smraw);
    const uint32_t Abase = abase + A_OFF;
    const uint32_t Bbase[2] = { abase + B0_OFF, abase + B1_OFF };

    const int tid = threadIdx.x;
    const int lane = tid & 31, warp = tid >> 5;
    const int wm = warp >> 2, wn = warp & 3;          // 2 x 4 warp grid, warp tile 64x32
    const int ptid = (wm << 5) | lane;                // 0..63 within pair
    const int q = lane & 3;
    const int bx = blockIdx.x, by = blockIdx.y;
    const int rowBase = by * 128;
    const int col0 = bx * (128 * SPLIT);

    const __nv_bfloat16* xg = g_xb + (size_t)rowBase * Dn;

    // group 0: A tile (128x128 bf16), all 256 threads
    #pragma unroll
    for (int i = 0; i < 8; i++) {
        int idx = tid + i * 256;
        int r = idx >> 4, f = idx & 15;
        cpa16(Abase + r * ROWB + f * 16, xg + (size_t)r * Dn + f * 8);
    }
    asm volatile("cp.async.commit_group;\n");

    // groups 1,2: this pair's 32-row slice of B tiles 0,1, rows permuted
    #pragma unroll
    for (int pb = 0; pb < 2; pb++) {
        const __nv_bfloat16* eg = g_eb + (size_t)(col0 + pb * 128) * Dn;
        #pragma unroll
        for (int i = 0; i < 8; i++) {
            int idx = ptid + i * 64;
            int rl = idx >> 4, f = idx & 15;
            int rs = (wn << 5) + rl;
            int rc = (wn << 5) + permB(rl);
            cpa16(Bbase[pb] + rs * ROWB + f * 16, eg + (size_t)rc * Dn + f * 8);
        }
        asm volatile("cp.async.commit_group;\n");
    }

    if (tid < 128) x2s[tid] = g_x2[rowBase + tid];
    ((float4*)e2s)[tid] = *(const float4*)(g_e2 + col0 + tid * 4);   // 1024 e2 values

    asm volatile("cp.async.wait_group 1;\n");          // A + B0 resident
    __syncthreads();

    const uint32_t aoff = (uint32_t)(lane & 15) * ROWB + ((uint32_t)(lane >> 4) << 4);
    const uint32_t boff = ((((uint32_t)lane >> 4) << 3) + (lane & 7)) * ROWB + (((lane >> 3) & 1) << 4);
    const uint32_t Aw = Abase + (wm * 64) * ROWB + aoff;

    float* dist = out + OFF_DIST;

    #pragma unroll 1
    for (int it = 0; it < SPLIT; it++) {
        const int colBase = col0 + it * 128;
        const int tileIdx = colBase >> 7;

        // e2 for this iter from smem (2 x LDS.128)
        const float* e2p = e2s + it * 128 + wn * 32 + 8 * q;
        float4 ea = *(const float4*)e2p;
        float4 eb2 = *(const float4*)(e2p + 4);
        float e2v[8] = { ea.x, ea.y, ea.z, ea.w, eb2.x, eb2.y, eb2.z, eb2.w };

        const uint32_t Bw = Bbase[it & 1] + (wn * 32) * ROWB + boff;
        float acc[4][4][4] = {};
        #pragma unroll
        for (int ks = 0; ks < 8; ks++) {
            const uint32_t kb = ks * 32;
            uint32_t a[4][4], b[2][4];
            #pragma unroll
            for (int mt = 0; mt < 4; mt++) ldsm4(a[mt], Aw + mt * (16 * ROWB) + kb);
            #pragma unroll
            for (int nt2 = 0; nt2 < 2; nt2++) ldsm4(b[nt2], Bw + nt2 * (16 * ROWB) + kb);
            #pragma unroll
            for (int mt = 0; mt < 4; mt++)
                #pragma unroll
                for (int nti = 0; nti < 4; nti++)
                    mma_bf16(acc[mt][nti], a[mt], &b[nti >> 1][(nti & 1) * 2]);
        }

        // epilogue: dist = x2 + e2 - 2*dot; thread holds 8 consecutive cols per (mt,half)
        #pragma unroll
        for (int mt = 0; mt < 4; mt++) {
            #pragma unroll
            for (int half = 0; half < 2; half++) {
                int r = wm * 64 + mt * 16 + half * 8 + (lane >> 2);
                size_t grow = (size_t)rowBase + r;
                float x2v = x2s[r];
                float* drow = dist + grow * Kn + colBase + wn * 32 + 8 * q;
                float d0 = fmaf(-2.0f, acc[mt][0][half * 2 + 0], x2v + e2v[0]);
                float d1 = fmaf(-2.0f, acc[mt][0][half * 2 + 1], x2v + e2v[1]);
                float d2 = fmaf(-2.0f, acc[mt][1][half * 2 + 0], x2v + e2v[2]);
                float d3 = fmaf(-2.0f, acc[mt][1][half * 2 + 1], x2v + e2v[3]);
                float d4 = fmaf(-2.0f, acc[mt][2][half * 2 + 0], x2v + e2v[4]);
                float d5 = fmaf(-2.0f, acc[mt][2][half * 2 + 1], x2v + e2v[5]);
                float d6 = fmaf(-2.0f, acc[mt][3][half * 2 + 0], x2v + e2v[6]);
                float d7 = fmaf(-2.0f, acc[mt][3][half * 2 + 1], x2v + e2v[7]);
                stg_cs_v4(drow,     d0, d1, d2, d3);
                stg_cs_v4(drow + 4, d4, d5, d6, d7);
                float minv = fminf(fminf(fminf(d0, d1), fminf(d2, d3)),
                                   fminf(fminf(d4, d5), fminf(d6, d7)));
                minv = fminf(minv, __shfl_xor_sync(0xffffffffu, minv, 1));
                minv = fminf(minv, __shfl_xor_sync(0xffffffffu, minv, 2));
                if (q == 0)
                    atomicMin(&g_tilemin[grow * 64 + tileIdx], __float_as_int(minv));
            }
        }

        // single pair-barrier: next iter's data drained + buffer released
        asm volatile("cp.async.wait_group 0;\n");
        asm volatile("bar.sync %0, 64;" :: "r"(1 + wn) : "memory");
        if (it + 2 < SPLIT) {
            const __nv_bfloat16* eg = g_eb + (size_t)(col0 + (it + 2) * 128) * Dn;
            #pragma unroll
            for (int i = 0; i < 8; i++) {
                int idx = ptid + i * 64;
                int rl = idx >> 4, f = idx & 15;
                int rs = (wn << 5) + rl;
                int rc = (wn << 5) + permB(rl);
                cpa16(Bbase[it & 1] + rs * ROWB + f * 16, eg + (size_t)rc * Dn + f * 8);
            }
            asm volatile("cp.async.commit_group;\n");
        }
    }
}

// ---------------- argmin refine (fast-path + exact fallback) + fused assign ----------------
__global__ void refine_kernel(const float* __restrict__ x, const float* __restrict__ e,
                              float* __restrict__ out) {
    int t = (blockIdx.x * blockDim.x + threadIdx.x) >> 5;
    int lane = threadIdx.x & 31;
    if (t >= Tn) return;
    const float* dist = out + OFF_DIST;

    float4 xa = ((const float4*)(x + (size_t)t * Dn))[lane];
    float m0 = __int_as_float(g_tilemin[(size_t)t * 64 + lane]);
    float m1 = __int_as_float(g_tilemin[(size_t)t * 64 + 32 + lane]);

    float ml = fminf(m0, m1);
    float gm = ml;
    #pragma unroll
    for (int s = 16; s; s >>= 1) gm = fminf(gm, __shfl_xor_sync(0xffffffffu, gm, s));

    unsigned msk = __ballot_sync(0xffffffffu, ml == gm);
    int srcLane = __ffs(msk) - 1;
    int myTile = (m0 <= m1) ? lane : lane + 32;
    int bestTile = __shfl_sync(0xffffffffu, myTile, srcLane);
    float contrib = (lane == srcLane) ? ((m0 <= m1) ? m1 : m0) : ml;
    float secTiles = contrib;
    #pragma unroll
    for (int s = 16; s; s >>= 1) secTiles = fminf(secTiles, __shfl_xor_sync(0xffffffffu, secTiles, s));

    float4 dv = ((const float4*)(dist + (size_t)t * Kn + bestTile * 128))[lane];
    int cb = bestTile * 128 + lane * 4;
    u64 k0 = ((u64)__float_as_uint(dv.x) << 32) | (unsigned)(cb + 0);
    u64 k1 = ((u64)__float_as_uint(dv.y) << 32) | (unsigned)(cb + 1);
    u64 k2 = ((u64)__float_as_uint(dv.z) << 32) | (unsigned)(cb + 2);
    u64 k3 = ((u64)__float_as_uint(dv.w) << 32) | (unsigned)(cb + 3);
    u64 a01 = min(k0, k1), b01 = max(k0, k1);
    u64 a23 = min(k2, k3), b23 = max(k2, k3);
    u64 kb = min(a01, a23);
    float run2 = fminf(__uint_as_float((uint32_t)(max(a01, a23) >> 32)),
                       fminf(__uint_as_float((uint32_t)(b01 >> 32)),
                             __uint_as_float((uint32_t)(b23 >> 32))));
    #pragma unroll
    for (int s = 16; s; s >>= 1) {
        u64 ko = __shfl_xor_sync(0xffffffffu, kb, s);
        float r2o = __shfl_xor_sync(0xffffffffu, run2, s);
        float loserv = __uint_as_float((uint32_t)(max(kb, ko) >> 32));
        run2 = fminf(fminf(run2, r2o), loserv);
        kb = min(kb, ko);
    }
    float bestv = __uint_as_float((uint32_t)(kb >> 32));
    int idx;
    if (fminf(secTiles, run2) - bestv > 0.5f) {
        idx = (int)(kb & 0xffffffffull);
    } else {
        float th = gm + 1.0f;
        float x2v = g_x2[t];
        u64 best = ~0ull;
        #pragma unroll
        for (int j2 = 0; j2 < 2; j2++) {
            float tv = j2 ? m1 : m0;
            unsigned m = __ballot_sync(0xffffffffu, tv < th);
            while (m) {
                int tl = __ffs(m) - 1; m &= m - 1;
                int tile = tl + 32 * j2;
                float4 dd = ((const float4*)(dist + (size_t)t * Kn + tile * 128))[lane];
                float dvals[4] = {dd.x, dd.y, dd.z, dd.w};
                #pragma unroll
                for (int qq = 0; qq < 4; qq++) {
                    unsigned lm = __ballot_sync(0xffffffffu, dvals[qq] < th);
                    while (lm) {
                        int src = __ffs(lm) - 1; lm &= lm - 1;
                        int col = tile * 128 + src * 4 + qq;
                        float4 ev = ((const float4*)(e + (size_t)col * Dn))[lane];
                        float p = xa.x * ev.x + xa.y * ev.y + xa.z * ev.z + xa.w * ev.w;
                        #pragma unroll
                        for (int s = 16; s; s >>= 1) p += __shfl_xor_sync(0xffffffffu, p, s);
                        float dex = x2v + g_e2[col] - 2.0f * p;
                        u64 kk = ((u64)__float_as_uint(dex) << 32) | (u64)(unsigned)col;
                        best = min(best, kk);
                    }
                }
            }
        }
        idx = (int)(best & 0xffffffffull);
    }

    float4 ev = ((const float4*)(e + (size_t)idx * Dn))[lane];
    ((float4*)(out + OFF_Q + (size_t)t * Dn))[lane] = ev;
    float* gp = g_es + (size_t)idx * Dn + lane * 4;
    atomicAdd(gp + 0, xa.x);
    atomicAdd(gp + 1, xa.y);
    atomicAdd(gp + 2, xa.z);
    atomicAdd(gp + 3, xa.w);
    if (lane == 0) {
        out[OFF_IDX + t] = (float)idx;
        atomicAdd(&g_cs[idx], 1.0f);
    }
}

// ---------------- fused EMA: cluster size, embed_avg, laplace-normalized embed ----------------
__global__ void ema_kernel(const float* __restrict__ cs_in, const float* __restrict__ ea,
                           float* __restrict__ out) {
    size_t i = (size_t)blockIdx.x * 256 + threadIdx.x;
    if (i >= (size_t)Kn * Dn) return;
    int k = (int)(i >> 7);
    float ncs = DECAYc * cs_in[k] + OMD * g_cs[k];
    if ((i & 127) == 0) out[OFF_NCS + k] = ncs;
    float nea = DECAYc * ea[i] + OMD * g_es[i];
    out[OFF_NEA + i] = nea;
    float total = DECAYc * g_sum_cs + OMD * (float)Tn;
    float norm = (ncs + EPSc) / (total + (float)Kn * EPSc);
    out[OFF_NE + i] = nea / norm;
}

extern "C" void kernel_launch(void* const* d_in, const int* in_sizes, int n_in,
                              void* d_out, int out_size) {
    const float* x     = (const float*)d_in[0];
    const float* embed = (const float*)d_in[1];
    const float* csz   = (const float*)d_in[2];
    const float* eavg  = (const float*)d_in[3];
    float* out = (float*)d_out;

    cudaFuncSetAttribute(gemm_kernel, cudaFuncAttributeMaxDynamicSharedMemorySize, GEMM_SMEM);

    convert_kernel<<<(Tn + Kn) / 8, 256>>>(x, embed, csz);
    gemm_kernel<<<dim3(Kn / (128 * SPLIT), Tn / 128), 256, GEMM_SMEM>>>(out);
    refine_kernel<<<Tn / 8, 256>>>(x, embed, out);
    ema_kernel<<<(Kn * Dn) / 256, 256>>>(csz, eavg, out);
}